// round 12
// baseline (speedup 1.0000x reference)
#include <cuda_runtime.h>

#define BB     32
#define IDF    64
#define RES    128
#define QL     (RES*RES)      // 16384
#define CDF    768
#define SL     18
#define ADIM   100
#define NSPLIT 64
#define KCH    (QL/NSPLIT)    // 256
#define SP     9              // s-pairs

#define K2_STAGE_FLOATS (8*1024)           // 8 channels x 1024 q = 32KB
#define K2_SMEM_FLOATS  (3*K2_STAGE_FLOATS + IDF*20 + 32)
#define K2_SMEM_BYTES   (K2_SMEM_FLOATS*4)

// Scratch (no cudaMalloc allowed)
__device__ float g_sourceT[BB*IDF*SL];        // [b][i][s]
__device__ float g_wctx2[BB*QL];              // [b][q]
__device__ float g_partial[NSPLIT*ADIM*BB];   // [split][a][b]
__device__ int   g_cnt[8];                    // per-a-group completion counters

__device__ __forceinline__ unsigned long long pack2(float lo, float hi){
    unsigned long long r;
    asm("mov.b64 %0, {%1,%2};" : "=l"(r) : "f"(lo), "f"(hi));
    return r;
}
__device__ __forceinline__ void unpack2(unsigned long long v, float &lo, float &hi){
    asm("mov.b64 {%0,%1}, %2;" : "=f"(lo), "=f"(hi) : "l"(v));
}
// d = a*b + d  (packed 2x fp32, sm_100+ FFMA2)
__device__ __forceinline__ void ffma2(unsigned long long &d, unsigned long long a, unsigned long long b){
    asm("fma.rn.f32x2 %0, %1, %2, %0;" : "+l"(d) : "l"(a), "l"(b));
}
__device__ __forceinline__ void cp_async16(unsigned smem_addr, const void* gptr){
    asm volatile("cp.async.cg.shared.global [%0], [%1], 16;" :: "r"(smem_addr), "l"(gptr));
}

// ---------------------------------------------------------------------------
// k1: sourceT[b,i,s] = sum_c conv_ctx_w[i,c] * context[b,c,s]
// This round: w row prefetched into regs (one LDG burst, kills serial LDG
// chain); context staged via cp.async, all 3 chunks issued up-front into 3
// buffers so staging latency overlaps compute. warp-per-(b,i), grid (8,32).
// ---------------------------------------------------------------------------
__global__ void __launch_bounds__(256) k1_sourceT(const float* __restrict__ ctx,
                                                  const float* __restrict__ w){
    const int b    = blockIdx.y;
    const int tid  = threadIdx.x;
    const int lane = tid & 31;
    const int i    = blockIdx.x * 8 + (tid >> 5);

    if (blockIdx.x == 0 && blockIdx.y == 0 && tid < 8) g_cnt[tid] = 0;

    __shared__ __align__(16) float sctx[3][256*SL];   // 3 x 18KB chunks
    const unsigned s_base = (unsigned)__cvta_generic_to_shared(&sctx[0][0]);

    // issue all 3 context chunks immediately (1152 float4 each)
    #pragma unroll
    for (int k = 0; k < 3; ++k){
        const char* src = (const char*)(ctx + (long long)b*CDF*SL + k*256*SL);
        #pragma unroll
        for (int idx = tid; idx < 256*SL/4; idx += 256)
            cp_async16(s_base + k*(256*SL*4) + idx*16, src + idx*16);
        asm volatile("cp.async.commit_group;");
    }

    // burst-prefetch this lane's 24 w values (front-batched LDGs)
    float wreg[24];
    const float* wr = w + i*CDF + lane;
    #pragma unroll
    for (int m = 0; m < 24; ++m) wreg[m] = __ldg(wr + m*32);

    float acc[SL];
    #pragma unroll
    for (int s = 0; s < SL; ++s) acc[s] = 0.f;

    #pragma unroll
    for (int k = 0; k < 3; ++k){
        if      (k == 0) asm volatile("cp.async.wait_group 2;");
        else if (k == 1) asm volatile("cp.async.wait_group 1;");
        else             asm volatile("cp.async.wait_group 0;");
        __syncthreads();
        #pragma unroll 2
        for (int j = 0; j < 8; ++j){
            const int c = lane + j*32;
            const float wv = wreg[k*8 + j];
            const float* cp = &sctx[k][c*SL];
            #pragma unroll
            for (int s = 0; s < SL; ++s) acc[s] = fmaf(wv, cp[s], acc[s]);
        }
    }

    #pragma unroll
    for (int off = 16; off; off >>= 1){
        #pragma unroll
        for (int s = 0; s < SL; ++s)
            acc[s] += __shfl_xor_sync(0xffffffffu, acc[s], off);
    }
    if (lane == 0){
        #pragma unroll
        for (int s = 0; s < SL; ++s)
            g_sourceT[b*IDF*SL + i*SL + s] = acc[s];
    }
}

// ---------------------------------------------------------------------------
// k2: fused scores GEMV + softmax + cs-dot. Proven 3-stage cp.async ring;
// this round 4 q/thread (-18% issue slots; MLP lives in smem so the
// occupancy drop to 2 CTAs/SM is safe). grid (16 qtiles, 32 b), 1024 q/blk.
// ---------------------------------------------------------------------------
__device__ __forceinline__ void k2_consume4(const float4 xv, const float* rowf,
                                            unsigned long long* a0,
                                            unsigned long long* a1,
                                            unsigned long long* a2,
                                            unsigned long long* a3){
    unsigned long long t0 = pack2(xv.x, xv.x);
    unsigned long long t1 = pack2(xv.y, xv.y);
    unsigned long long t2 = pack2(xv.z, xv.z);
    unsigned long long t3 = pack2(xv.w, xv.w);
    const ulonglong2* r2 = reinterpret_cast<const ulonglong2*>(rowf);
    ulonglong2 v01 = r2[0];          // s0..s3
    ulonglong2 v23 = r2[1];          // s4..s7
    ulonglong2 v45 = r2[2];          // s8..s11
    ulonglong2 v67 = r2[3];          // s12..s15
    unsigned long long v8 = reinterpret_cast<const unsigned long long*>(rowf)[8]; // s16,s17
    ffma2(a0[0], t0, v01.x); ffma2(a1[0], t1, v01.x); ffma2(a2[0], t2, v01.x); ffma2(a3[0], t3, v01.x);
    ffma2(a0[1], t0, v01.y); ffma2(a1[1], t1, v01.y); ffma2(a2[1], t2, v01.y); ffma2(a3[1], t3, v01.y);
    ffma2(a0[2], t0, v23.x); ffma2(a1[2], t1, v23.x); ffma2(a2[2], t2, v23.x); ffma2(a3[2], t3, v23.x);
    ffma2(a0[3], t0, v23.y); ffma2(a1[3], t1, v23.y); ffma2(a2[3], t2, v23.y); ffma2(a3[3], t3, v23.y);
    ffma2(a0[4], t0, v45.x); ffma2(a1[4], t1, v45.x); ffma2(a2[4], t2, v45.x); ffma2(a3[4], t3, v45.x);
    ffma2(a0[5], t0, v45.y); ffma2(a1[5], t1, v45.y); ffma2(a2[5], t2, v45.y); ffma2(a3[5], t3, v45.y);
    ffma2(a0[6], t0, v67.x); ffma2(a1[6], t1, v67.x); ffma2(a2[6], t2, v67.x); ffma2(a3[6], t3, v67.x);
    ffma2(a0[7], t0, v67.y); ffma2(a1[7], t1, v67.y); ffma2(a2[7], t2, v67.y); ffma2(a3[7], t3, v67.y);
    ffma2(a0[8], t0, v8   ); ffma2(a1[8], t1, v8   ); ffma2(a2[8], t2, v8   ); ffma2(a3[8], t3, v8   );
}

__device__ __forceinline__ float k2_finish1(const unsigned long long* sc,
                                            const float* scs, float cb){
    float sa[SL];
    #pragma unroll
    for (int p = 0; p < SP; ++p) unpack2(sc[p], sa[2*p], sa[2*p+1]);
    float d = 0.f, n = 0.f;
    #pragma unroll
    for (int s = 0; s < SL; ++s){
        float e = __expf(sa[s]);     // no max-subtract: |score| << 88
        d += e;
        n = fmaf(e, scs[s], n);
    }
    return n/d + cb;
}

__global__ void __launch_bounds__(256) k2_attn(const float* __restrict__ x,
                                               const float* __restrict__ conv_w,
                                               const float* __restrict__ conv_b){
    extern __shared__ __align__(16) float dsm[];
    float* sx   = dsm;                          // 3 stages x 8192 floats
    float* ssrc = dsm + 3*K2_STAGE_FLOATS;      // 64 rows, stride 20
    float* scs  = ssrc + IDF*20;                // 18 floats

    const int b   = blockIdx.y;
    const int tid = threadIdx.x;
    const int q0  = blockIdx.x * 1024;
    const float* xbase = x + (long long)b*IDF*QL + q0;
    const unsigned sx_base = (unsigned)__cvta_generic_to_shared(sx);
    const int offb = tid * 16;                  // 16B slot within each 4KB row

    // prologue: start stages 0 and 1 (8 cp.async each)
    #pragma unroll
    for (int ch = 0; ch < 8; ++ch)
        cp_async16(sx_base + ch*4096 + offb,
                   (const char*)(xbase + (long long)ch*QL) + offb);
    asm volatile("cp.async.commit_group;");
    #pragma unroll
    for (int ch = 0; ch < 8; ++ch)
        cp_async16(sx_base + K2_STAGE_FLOATS*4 + ch*4096 + offb,
                   (const char*)(xbase + (long long)(8+ch)*QL) + offb);
    asm volatile("cp.async.commit_group;");

    // stage sourceT rows while prologue loads fly, then compute cs inline
    for (int idx = tid; idx < IDF*SL; idx += 256){
        int i = idx / SL, s = idx - i*SL;
        ssrc[i*20 + s] = g_sourceT[b*IDF*SL + idx];
    }
    __syncthreads();
    if (tid < SL){
        float c = 0.f;
        #pragma unroll 8
        for (int i = 0; i < IDF; ++i)
            c = fmaf(__ldg(conv_w + i), ssrc[i*20 + tid], c);
        scs[tid] = c;          // consumed in epilogue; chunk-loop syncs cover it
    }

    unsigned long long a0[SP], a1[SP], a2[SP], a3[SP];
    #pragma unroll
    for (int p = 0; p < SP; ++p){ a0[p]=0ULL; a1[p]=0ULL; a2[p]=0ULL; a3[p]=0ULL; }

    #pragma unroll 1
    for (int c = 0; c < 8; ++c){
        if (c == 7) asm volatile("cp.async.wait_group 0;");
        else        asm volatile("cp.async.wait_group 1;");   // stages <= c done
        __syncthreads();            // visibility + slot-reuse safety
        if (c < 6){                 // issue stage c+2 into slot (c+2)%3
            const int nslot = (c+2) % 3;
            const float* xc = xbase + (long long)(c+2)*8*QL;
            #pragma unroll
            for (int ch = 0; ch < 8; ++ch)
                cp_async16(sx_base + nslot*(K2_STAGE_FLOATS*4) + ch*4096 + offb,
                           (const char*)(xc + (long long)ch*QL) + offb);
            asm volatile("cp.async.commit_group;");
        }
        const float* rowc = ssrc + c*(8*20);
        const float* sxc  = sx + (c % 3)*K2_STAGE_FLOATS + tid*4;
        #pragma unroll
        for (int j = 0; j < 8; ++j){
            float4 xv = *reinterpret_cast<const float4*>(sxc + j*1024);
            k2_consume4(xv, rowc + j*20, a0, a1, a2, a3);
        }
    }

    const float cb = conv_b[0];
    float4 o4;
    o4.x = k2_finish1(a0, scs, cb);
    o4.y = k2_finish1(a1, scs, cb);
    o4.z = k2_finish1(a2, scs, cb);
    o4.w = k2_finish1(a3, scs, cb);
    *reinterpret_cast<float4*>(&g_wctx2[b*QL + q0 + tid*4]) = o4;
}

// ---------------------------------------------------------------------------
// k3: split-K FC partials + fused final reduce (R11-proven).
// ---------------------------------------------------------------------------
__global__ void __launch_bounds__(256) k3_fc(const float* __restrict__ fcw,
                                             const float* __restrict__ fcb,
                                             float* __restrict__ out){
    const int split = blockIdx.x;
    const int k0    = split * KCH;
    const int tid   = threadIdx.x;
    const int lane  = tid & 31;
    const int w     = tid >> 5;

    __shared__ float sm[KCH*33];   // [k][b], padded (33.8 KB)
    for (int idx = tid; idx < BB*KCH; idx += 256){
        int b = idx >> 8;          // /256
        int k = idx & 255;
        sm[k*33 + b] = g_wctx2[b*QL + k0 + k];
    }
    __syncthreads();

    const int a0 = blockIdx.y * 16 + w * 2;   // a-pair {a0, a0+1}
    if (a0 < ADIM){
        const float4* f0 = reinterpret_cast<const float4*>(fcw + (long long)(a0  )*QL + k0);
        const float4* f1 = reinterpret_cast<const float4*>(fcw + (long long)(a0+1)*QL + k0);
        float acc0 = 0.f, acc1 = 0.f;
        #pragma unroll 8
        for (int kq = 0; kq < KCH/4; ++kq){
            float4 x0 = __ldg(f0 + kq);
            float4 x1 = __ldg(f1 + kq);
            const int k = kq*4;
            float v0 = sm[(k+0)*33 + lane];
            float v1 = sm[(k+1)*33 + lane];
            float v2 = sm[(k+2)*33 + lane];
            float v3 = sm[(k+3)*33 + lane];
            acc0 = fmaf(x0.x, v0, acc0);  acc1 = fmaf(x1.x, v0, acc1);
            acc0 = fmaf(x0.y, v1, acc0);  acc1 = fmaf(x1.y, v1, acc1);
            acc0 = fmaf(x0.z, v2, acc0);  acc1 = fmaf(x1.z, v2, acc1);
            acc0 = fmaf(x0.w, v3, acc0);  acc1 = fmaf(x1.w, v3, acc1);
        }
        g_partial[split*(ADIM*BB) + (a0  )*BB + lane] = acc0;
        g_partial[split*(ADIM*BB) + (a0+1)*BB + lane] = acc1;
    }

    __threadfence();
    __syncthreads();
    __shared__ int is_last;
    if (tid == 0)
        is_last = (atomicAdd(&g_cnt[blockIdx.y], 1) == NSPLIT - 1);
    __syncthreads();
    if (!is_last || a0 >= ADIM) return;

    float r0 = 0.f, r1 = 0.f;
    const float* p0 = g_partial + (a0  )*BB + lane;
    const float* p1 = g_partial + (a0+1)*BB + lane;
    #pragma unroll 8
    for (int sp = 0; sp < NSPLIT; ++sp){
        r0 += __ldcg(p0 + sp*(ADIM*BB));
        r1 += __ldcg(p1 + sp*(ADIM*BB));
    }
    out[lane*ADIM + a0    ] = r0 + fcb[a0    ];
    out[lane*ADIM + a0 + 1] = r1 + fcb[a0 + 1];
}

extern "C" void kernel_launch(void* const* d_in, const int* in_sizes, int n_in,
                              void* d_out, int out_size){
    const float* inputs     = (const float*)d_in[0];  // [32,64,128,128]
    const float* context    = (const float*)d_in[1];  // [32,768,18]
    const float* conv_ctx_w = (const float*)d_in[2];  // [64,768]
    const float* conv_w     = (const float*)d_in[3];  // [64]
    const float* conv_b     = (const float*)d_in[4];  // [1]
    const float* fc_w       = (const float*)d_in[5];  // [100,16384]
    const float* fc_b       = (const float*)d_in[6];  // [100]
    float* out = (float*)d_out;                        // [32,100]

    cudaFuncSetAttribute(k2_attn, cudaFuncAttributeMaxDynamicSharedMemorySize,
                         K2_SMEM_BYTES);

    k1_sourceT<<<dim3(8, BB), 256>>>(context, conv_ctx_w);
    k2_attn   <<<dim3(QL/1024, BB), 256, K2_SMEM_BYTES>>>(inputs, conv_w, conv_b);
    k3_fc     <<<dim3(NSPLIT, 7), 256>>>(fc_w, fc_b, out);
}

// round 13
// speedup vs baseline: 1.0055x; 1.0055x over previous
#include <cuda_runtime.h>

#define BB     32
#define IDF    64
#define RES    128
#define QL     (RES*RES)      // 16384
#define CDF    768
#define SL     18
#define ADIM   100
#define NSPLIT 64
#define KCH    (QL/NSPLIT)    // 256
#define SP     9              // s-pairs

#define K2_STAGE_FLOATS (8*512)            // 8 channels x 512 q = 16KB
#define K2_SMEM_FLOATS  (3*K2_STAGE_FLOATS + IDF*20 + 32)
#define K2_SMEM_BYTES   (K2_SMEM_FLOATS*4)

// Scratch (no cudaMalloc allowed)
__device__ float g_sourceT[BB*IDF*SL];        // [b][i][s]
__device__ float g_wctx2[BB*QL];              // [b][q]
__device__ float g_partial[NSPLIT*ADIM*BB];   // [split][a][b]
__device__ int   g_cnt[8];                    // per-a-group completion counters

__device__ __forceinline__ unsigned long long pack2(float lo, float hi){
    unsigned long long r;
    asm("mov.b64 %0, {%1,%2};" : "=l"(r) : "f"(lo), "f"(hi));
    return r;
}
__device__ __forceinline__ void unpack2(unsigned long long v, float &lo, float &hi){
    asm("mov.b64 {%0,%1}, %2;" : "=f"(lo), "=f"(hi) : "l"(v));
}
// d = a*b + d  (packed 2x fp32, sm_100+ FFMA2)
__device__ __forceinline__ void ffma2(unsigned long long &d, unsigned long long a, unsigned long long b){
    asm("fma.rn.f32x2 %0, %1, %2, %0;" : "+l"(d) : "l"(a), "l"(b));
}
__device__ __forceinline__ void cp_async16(unsigned smem_addr, const void* gptr){
    asm volatile("cp.async.cg.shared.global [%0], [%1], 16;" :: "r"(smem_addr), "l"(gptr));
}

// ---------------------------------------------------------------------------
// k1: sourceT[b,i,s] = sum_c conv_ctx_w[i,c] * context[b,c,s]
// This round: each warp owns FOUR i-rows (acc in 72 regs) so every LDS of
// context feeds 4 FMAs -> crossbar traffic per SM cut ~2x, redundancy 4x
// less. grid (2 igroups, 32 b), 256 threads, one 54KB stage, one barrier.
// ---------------------------------------------------------------------------
__global__ void __launch_bounds__(256) k1_sourceT(const float* __restrict__ ctx,
                                                  const float* __restrict__ w){
    const int b    = blockIdx.y;
    const int tid  = threadIdx.x;
    const int lane = tid & 31;
    const int i0   = blockIdx.x * 32 + (tid >> 5) * 4;   // 4 i-rows per warp

    if (blockIdx.x == 0 && blockIdx.y == 0 && tid < 8) g_cnt[tid] = 0;

    __shared__ float sctx[CDF*SL];     // 54 KB: full context[b]

    // stage whole context[b] (3456 float4)
    const float4* src = reinterpret_cast<const float4*>(ctx + (long long)b*CDF*SL);
    float4* dst = reinterpret_cast<float4*>(sctx);
    for (int idx = tid; idx < CDF*SL/4; idx += 256) dst[idx] = src[idx];
    __syncthreads();

    float a0[SL], a1[SL], a2[SL], a3[SL];
    #pragma unroll
    for (int s = 0; s < SL; ++s){ a0[s]=0.f; a1[s]=0.f; a2[s]=0.f; a3[s]=0.f; }

    const float* w0 = w + (i0+0)*CDF + lane;
    const float* w1 = w + (i0+1)*CDF + lane;
    const float* w2 = w + (i0+2)*CDF + lane;
    const float* w3 = w + (i0+3)*CDF + lane;

    #pragma unroll 2
    for (int j = 0; j < 24; ++j){
        const int c = lane + j*32;
        const float wv0 = __ldg(w0 + j*32);
        const float wv1 = __ldg(w1 + j*32);
        const float wv2 = __ldg(w2 + j*32);
        const float wv3 = __ldg(w3 + j*32);
        const float* cp = &sctx[c*SL];
        #pragma unroll
        for (int s = 0; s < SL; ++s){
            const float v = cp[s];
            a0[s] = fmaf(wv0, v, a0[s]);
            a1[s] = fmaf(wv1, v, a1[s]);
            a2[s] = fmaf(wv2, v, a2[s]);
            a3[s] = fmaf(wv3, v, a3[s]);
        }
    }

    // butterfly reduce across lanes (c-partials) for all 4 rows
    #pragma unroll
    for (int off = 16; off; off >>= 1){
        #pragma unroll
        for (int s = 0; s < SL; ++s){
            a0[s] += __shfl_xor_sync(0xffffffffu, a0[s], off);
            a1[s] += __shfl_xor_sync(0xffffffffu, a1[s], off);
            a2[s] += __shfl_xor_sync(0xffffffffu, a2[s], off);
            a3[s] += __shfl_xor_sync(0xffffffffu, a3[s], off);
        }
    }
    if (lane == 0){
        float* o = g_sourceT + b*IDF*SL + i0*SL;
        #pragma unroll
        for (int s = 0; s < SL; ++s){
            o[0*SL + s] = a0[s];
            o[1*SL + s] = a1[s];
            o[2*SL + s] = a2[s];
            o[3*SL + s] = a3[s];
        }
    }
}

// ---------------------------------------------------------------------------
// k2: fused scores GEMV + softmax + cs-dot. R11-proven 3-stage cp.async
// ring, 2 q/thread (34.9us measured). UNCHANGED this round.
// ---------------------------------------------------------------------------
__device__ __forceinline__ void k2_consume(const float2 xv, const float* rowf,
                                           unsigned long long* a0,
                                           unsigned long long* a1){
    unsigned long long t0 = pack2(xv.x, xv.x);
    unsigned long long t1 = pack2(xv.y, xv.y);
    const ulonglong2* r2 = reinterpret_cast<const ulonglong2*>(rowf);
    ulonglong2 v01 = r2[0];          // s0..s3
    ulonglong2 v23 = r2[1];          // s4..s7
    ulonglong2 v45 = r2[2];          // s8..s11
    ulonglong2 v67 = r2[3];          // s12..s15
    unsigned long long v8 = reinterpret_cast<const unsigned long long*>(rowf)[8]; // s16,s17
    ffma2(a0[0], t0, v01.x); ffma2(a1[0], t1, v01.x);
    ffma2(a0[1], t0, v01.y); ffma2(a1[1], t1, v01.y);
    ffma2(a0[2], t0, v23.x); ffma2(a1[2], t1, v23.x);
    ffma2(a0[3], t0, v23.y); ffma2(a1[3], t1, v23.y);
    ffma2(a0[4], t0, v45.x); ffma2(a1[4], t1, v45.x);
    ffma2(a0[5], t0, v45.y); ffma2(a1[5], t1, v45.y);
    ffma2(a0[6], t0, v67.x); ffma2(a1[6], t1, v67.x);
    ffma2(a0[7], t0, v67.y); ffma2(a1[7], t1, v67.y);
    ffma2(a0[8], t0, v8   ); ffma2(a1[8], t1, v8   );
}

__global__ void __launch_bounds__(256) k2_attn(const float* __restrict__ x,
                                               const float* __restrict__ conv_w,
                                               const float* __restrict__ conv_b){
    extern __shared__ __align__(16) float dsm[];
    float* sx   = dsm;                          // 3 stages x 4096 floats
    float* ssrc = dsm + 3*K2_STAGE_FLOATS;      // 64 rows, stride 20
    float* scs  = ssrc + IDF*20;                // 18 floats

    const int b   = blockIdx.y;
    const int tid = threadIdx.x;
    const int q0  = blockIdx.x * 512;
    const float* xbase = x + (long long)b*IDF*QL + q0;
    const unsigned sx_base = (unsigned)__cvta_generic_to_shared(sx);

    // per-thread copy slots: 4x 16B per stage (16KB / 256 threads)
    const int row0 = tid >> 7;            // 0..1
    const int off0 = (tid & 127) * 16;    // byte offset within 2KB row

    // prologue: start stages 0 and 1 immediately
    #pragma unroll
    for (int u = 0; u < 4; ++u){
        int ch = row0 + u*2;
        cp_async16(sx_base + ch*2048 + off0,
                   (const char*)(xbase + (long long)ch*QL) + off0);
    }
    asm volatile("cp.async.commit_group;");
    #pragma unroll
    for (int u = 0; u < 4; ++u){
        int ch = row0 + u*2;
        cp_async16(sx_base + 1*(K2_STAGE_FLOATS*4) + ch*2048 + off0,
                   (const char*)(xbase + (long long)(8 + ch)*QL) + off0);
    }
    asm volatile("cp.async.commit_group;");

    // stage sourceT rows while prologue loads fly, then compute cs inline
    for (int idx = tid; idx < IDF*SL; idx += 256){
        int i = idx / SL, s = idx - i*SL;
        ssrc[i*20 + s] = g_sourceT[b*IDF*SL + idx];
    }
    __syncthreads();
    if (tid < SL){
        float c = 0.f;
        #pragma unroll 8
        for (int i = 0; i < IDF; ++i)
            c = fmaf(__ldg(conv_w + i), ssrc[i*20 + tid], c);
        scs[tid] = c;          // consumed in epilogue; chunk-loop syncs cover it
    }

    unsigned long long a0[SP], a1[SP];
    #pragma unroll
    for (int p = 0; p < SP; ++p){ a0[p]=0ULL; a1[p]=0ULL; }

    #pragma unroll 1
    for (int c = 0; c < 8; ++c){
        if (c == 7) asm volatile("cp.async.wait_group 0;");
        else        asm volatile("cp.async.wait_group 1;");   // stages <= c done
        __syncthreads();            // cross-thread visibility + slot reuse safety
        if (c < 6){                 // issue stage c+2 into slot (c+2)%3
            const int nslot = (c+2) % 3;
            const float* xc = xbase + (long long)(c+2)*8*QL;
            #pragma unroll
            for (int u = 0; u < 4; ++u){
                int ch = row0 + u*2;
                cp_async16(sx_base + nslot*(K2_STAGE_FLOATS*4) + ch*2048 + off0,
                           (const char*)(xc + (long long)ch*QL) + off0);
            }
            asm volatile("cp.async.commit_group;");
        }
        const float* rowc = ssrc + c*(8*20);
        const float* sxc  = sx + (c % 3)*K2_STAGE_FLOATS + tid*2;
        #pragma unroll
        for (int j = 0; j < 8; ++j){
            float2 xv = *reinterpret_cast<const float2*>(sxc + j*512);
            k2_consume(xv, rowc + j*20, a0, a1);
        }
    }

    // epilogue: softmax (max-free: |score| << 88) + cs dot
    float sa[SL], sb[SL];
    #pragma unroll
    for (int p = 0; p < SP; ++p){
        unpack2(a0[p], sa[2*p], sa[2*p+1]);
        unpack2(a1[p], sb[2*p], sb[2*p+1]);
    }
    float d0 = 0.f, d1 = 0.f, n0 = 0.f, n1 = 0.f;
    #pragma unroll
    for (int s = 0; s < SL; ++s){
        float e0 = __expf(sa[s]);
        float e1 = __expf(sb[s]);
        float cc = scs[s];
        d0 += e0; d1 += e1;
        n0 = fmaf(e0, cc, n0);
        n1 = fmaf(e1, cc, n1);
    }
    const float cb = conv_b[0];
    float2 o2 = make_float2(n0/d0 + cb, n1/d1 + cb);
    *reinterpret_cast<float2*>(&g_wctx2[b*QL + q0 + tid*2]) = o2;
}

// ---------------------------------------------------------------------------
// k3: split-K FC partials + fused final reduce (R11-proven).
// ---------------------------------------------------------------------------
__global__ void __launch_bounds__(256) k3_fc(const float* __restrict__ fcw,
                                             const float* __restrict__ fcb,
                                             float* __restrict__ out){
    const int split = blockIdx.x;
    const int k0    = split * KCH;
    const int tid   = threadIdx.x;
    const int lane  = tid & 31;
    const int w     = tid >> 5;

    __shared__ float sm[KCH*33];   // [k][b], padded (33.8 KB)
    for (int idx = tid; idx < BB*KCH; idx += 256){
        int b = idx >> 8;          // /256
        int k = idx & 255;
        sm[k*33 + b] = g_wctx2[b*QL + k0 + k];
    }
    __syncthreads();

    const int a0 = blockIdx.y * 16 + w * 2;   // a-pair {a0, a0+1}
    if (a0 < ADIM){
        const float4* f0 = reinterpret_cast<const float4*>(fcw + (long long)(a0  )*QL + k0);
        const float4* f1 = reinterpret_cast<const float4*>(fcw + (long long)(a0+1)*QL + k0);
        float acc0 = 0.f, acc1 = 0.f;
        #pragma unroll 8
        for (int kq = 0; kq < KCH/4; ++kq){
            float4 x0 = __ldg(f0 + kq);
            float4 x1 = __ldg(f1 + kq);
            const int k = kq*4;
            float v0 = sm[(k+0)*33 + lane];
            float v1 = sm[(k+1)*33 + lane];
            float v2 = sm[(k+2)*33 + lane];
            float v3 = sm[(k+3)*33 + lane];
            acc0 = fmaf(x0.x, v0, acc0);  acc1 = fmaf(x1.x, v0, acc1);
            acc0 = fmaf(x0.y, v1, acc0);  acc1 = fmaf(x1.y, v1, acc1);
            acc0 = fmaf(x0.z, v2, acc0);  acc1 = fmaf(x1.z, v2, acc1);
            acc0 = fmaf(x0.w, v3, acc0);  acc1 = fmaf(x1.w, v3, acc1);
        }
        g_partial[split*(ADIM*BB) + (a0  )*BB + lane] = acc0;
        g_partial[split*(ADIM*BB) + (a0+1)*BB + lane] = acc1;
    }

    __threadfence();
    __syncthreads();
    __shared__ int is_last;
    if (tid == 0)
        is_last = (atomicAdd(&g_cnt[blockIdx.y], 1) == NSPLIT - 1);
    __syncthreads();
    if (!is_last || a0 >= ADIM) return;

    float r0 = 0.f, r1 = 0.f;
    const float* p0 = g_partial + (a0  )*BB + lane;
    const float* p1 = g_partial + (a0+1)*BB + lane;
    #pragma unroll 8
    for (int sp = 0; sp < NSPLIT; ++sp){
        r0 += __ldcg(p0 + sp*(ADIM*BB));
        r1 += __ldcg(p1 + sp*(ADIM*BB));
    }
    out[lane*ADIM + a0    ] = r0 + fcb[a0    ];
    out[lane*ADIM + a0 + 1] = r1 + fcb[a0 + 1];
}

extern "C" void kernel_launch(void* const* d_in, const int* in_sizes, int n_in,
                              void* d_out, int out_size){
    const float* inputs     = (const float*)d_in[0];  // [32,64,128,128]
    const float* context    = (const float*)d_in[1];  // [32,768,18]
    const float* conv_ctx_w = (const float*)d_in[2];  // [64,768]
    const float* conv_w     = (const float*)d_in[3];  // [64]
    const float* conv_b     = (const float*)d_in[4];  // [1]
    const float* fc_w       = (const float*)d_in[5];  // [100,16384]
    const float* fc_b       = (const float*)d_in[6];  // [100]
    float* out = (float*)d_out;                        // [32,100]

    cudaFuncSetAttribute(k2_attn, cudaFuncAttributeMaxDynamicSharedMemorySize,
                         K2_SMEM_BYTES);

    k1_sourceT<<<dim3(2, BB), 256>>>(context, conv_ctx_w);
    k2_attn   <<<dim3(QL/512, BB), 256, K2_SMEM_BYTES>>>(inputs, conv_w, conv_b);
    k3_fc     <<<dim3(NSPLIT, 7), 256>>>(fc_w, fc_b, out);
}

// round 14
// speedup vs baseline: 1.1980x; 1.1915x over previous
#include <cuda_runtime.h>

#define BB     32
#define IDF    64
#define RES    128
#define QL     (RES*RES)      // 16384
#define CDF    768
#define SL     18
#define ADIM   100
#define NSPLIT 64
#define KCH    (QL/NSPLIT)    // 256
#define SP     9              // s-pairs

#define K2_STAGE_FLOATS (8*512)            // 8 channels x 512 q = 16KB
#define K2_SMEM_FLOATS  (3*K2_STAGE_FLOATS + IDF*20 + 32)
#define K2_SMEM_BYTES   (K2_SMEM_FLOATS*4)

// Scratch (no cudaMalloc allowed)
__device__ float g_sourceT[BB*IDF*SL];        // [b][i][s]
__device__ float g_wctx2[BB*QL];              // [b][q]
__device__ float g_partial[NSPLIT*ADIM*BB];   // [split][a][b]

__device__ __forceinline__ unsigned long long pack2(float lo, float hi){
    unsigned long long r;
    asm("mov.b64 %0, {%1,%2};" : "=l"(r) : "f"(lo), "f"(hi));
    return r;
}
__device__ __forceinline__ void unpack2(unsigned long long v, float &lo, float &hi){
    asm("mov.b64 {%0,%1}, %2;" : "=f"(lo), "=f"(hi) : "l"(v));
}
// d = a*b + d  (packed 2x fp32, sm_100+ FFMA2)
__device__ __forceinline__ void ffma2(unsigned long long &d, unsigned long long a, unsigned long long b){
    asm("fma.rn.f32x2 %0, %1, %2, %0;" : "+l"(d) : "l"(a), "l"(b));
}
__device__ __forceinline__ void cp_async16(unsigned smem_addr, const void* gptr){
    asm volatile("cp.async.cg.shared.global [%0], [%1], 16;" :: "r"(smem_addr), "l"(gptr));
}

// ---------------------------------------------------------------------------
// k1: sourceT[b,i,s] = sum_c conv_ctx_w[i,c] * context[b,c,s]
// R3-PROVEN VERSION (10.8us measured). Frozen.
// ---------------------------------------------------------------------------
__global__ void __launch_bounds__(256) k1_sourceT(const float* __restrict__ ctx,
                                                  const float* __restrict__ w){
    const int b    = blockIdx.y;
    const int tid  = threadIdx.x;
    const int lane = tid & 31;
    const int i    = blockIdx.x * 8 + (tid >> 5);

    __shared__ float sctx[384*SL];     // 27 KB chunk of context[b]

    float acc[SL];
    #pragma unroll
    for (int s = 0; s < SL; ++s) acc[s] = 0.f;

    for (int c0 = 0; c0 < CDF; c0 += 384){
        __syncthreads();
        const float4* src = reinterpret_cast<const float4*>(ctx + (long long)b*CDF*SL + c0*SL);
        float4* dst = reinterpret_cast<float4*>(sctx);
        #pragma unroll
        for (int idx = tid; idx < 384*SL/4; idx += 256) dst[idx] = src[idx];
        __syncthreads();

        const float* wr = w + i*CDF + c0;
        #pragma unroll 4
        for (int j = 0; j < 12; ++j){
            const int c = lane + j*32;
            const float wv = __ldg(wr + c);
            const float* cp = &sctx[c*SL];
            #pragma unroll
            for (int s = 0; s < SL; ++s) acc[s] = fmaf(wv, cp[s], acc[s]);
        }
    }

    #pragma unroll
    for (int off = 16; off; off >>= 1){
        #pragma unroll
        for (int s = 0; s < SL; ++s)
            acc[s] += __shfl_xor_sync(0xffffffffu, acc[s], off);
    }
    if (lane == 0){
        #pragma unroll
        for (int s = 0; s < SL; ++s)
            g_sourceT[b*IDF*SL + i*SL + s] = acc[s];
    }
}

// ---------------------------------------------------------------------------
// k2: fused scores GEMV + softmax + cs-dot. R11-PROVEN 3-stage cp.async
// ring, 2 q/thread (34.9us measured). Frozen.
// ---------------------------------------------------------------------------
__device__ __forceinline__ void k2_consume(const float2 xv, const float* rowf,
                                           unsigned long long* a0,
                                           unsigned long long* a1){
    unsigned long long t0 = pack2(xv.x, xv.x);
    unsigned long long t1 = pack2(xv.y, xv.y);
    const ulonglong2* r2 = reinterpret_cast<const ulonglong2*>(rowf);
    ulonglong2 v01 = r2[0];          // s0..s3
    ulonglong2 v23 = r2[1];          // s4..s7
    ulonglong2 v45 = r2[2];          // s8..s11
    ulonglong2 v67 = r2[3];          // s12..s15
    unsigned long long v8 = reinterpret_cast<const unsigned long long*>(rowf)[8]; // s16,s17
    ffma2(a0[0], t0, v01.x); ffma2(a1[0], t1, v01.x);
    ffma2(a0[1], t0, v01.y); ffma2(a1[1], t1, v01.y);
    ffma2(a0[2], t0, v23.x); ffma2(a1[2], t1, v23.x);
    ffma2(a0[3], t0, v23.y); ffma2(a1[3], t1, v23.y);
    ffma2(a0[4], t0, v45.x); ffma2(a1[4], t1, v45.x);
    ffma2(a0[5], t0, v45.y); ffma2(a1[5], t1, v45.y);
    ffma2(a0[6], t0, v67.x); ffma2(a1[6], t1, v67.x);
    ffma2(a0[7], t0, v67.y); ffma2(a1[7], t1, v67.y);
    ffma2(a0[8], t0, v8   ); ffma2(a1[8], t1, v8   );
}

__global__ void __launch_bounds__(256) k2_attn(const float* __restrict__ x,
                                               const float* __restrict__ conv_w,
                                               const float* __restrict__ conv_b){
    extern __shared__ __align__(16) float dsm[];
    float* sx   = dsm;                          // 3 stages x 4096 floats
    float* ssrc = dsm + 3*K2_STAGE_FLOATS;      // 64 rows, stride 20
    float* scs  = ssrc + IDF*20;                // 18 floats

    const int b   = blockIdx.y;
    const int tid = threadIdx.x;
    const int q0  = blockIdx.x * 512;
    const float* xbase = x + (long long)b*IDF*QL + q0;
    const unsigned sx_base = (unsigned)__cvta_generic_to_shared(sx);

    // per-thread copy slots: 4x 16B per stage (16KB / 256 threads)
    const int row0 = tid >> 7;            // 0..1
    const int off0 = (tid & 127) * 16;    // byte offset within 2KB row

    // prologue: start stages 0 and 1 immediately
    #pragma unroll
    for (int u = 0; u < 4; ++u){
        int ch = row0 + u*2;
        cp_async16(sx_base + ch*2048 + off0,
                   (const char*)(xbase + (long long)ch*QL) + off0);
    }
    asm volatile("cp.async.commit_group;");
    #pragma unroll
    for (int u = 0; u < 4; ++u){
        int ch = row0 + u*2;
        cp_async16(sx_base + 1*(K2_STAGE_FLOATS*4) + ch*2048 + off0,
                   (const char*)(xbase + (long long)(8 + ch)*QL) + off0);
    }
    asm volatile("cp.async.commit_group;");

    // stage sourceT rows while prologue loads fly, then compute cs inline
    for (int idx = tid; idx < IDF*SL; idx += 256){
        int i = idx / SL, s = idx - i*SL;
        ssrc[i*20 + s] = g_sourceT[b*IDF*SL + idx];
    }
    __syncthreads();
    if (tid < SL){
        float c = 0.f;
        #pragma unroll 8
        for (int i = 0; i < IDF; ++i)
            c = fmaf(__ldg(conv_w + i), ssrc[i*20 + tid], c);
        scs[tid] = c;          // consumed in epilogue; chunk-loop syncs cover it
    }

    unsigned long long a0[SP], a1[SP];
    #pragma unroll
    for (int p = 0; p < SP; ++p){ a0[p]=0ULL; a1[p]=0ULL; }

    #pragma unroll 1
    for (int c = 0; c < 8; ++c){
        if (c == 7) asm volatile("cp.async.wait_group 0;");
        else        asm volatile("cp.async.wait_group 1;");   // stages <= c done
        __syncthreads();            // cross-thread visibility + slot reuse safety
        if (c < 6){                 // issue stage c+2 into slot (c+2)%3
            const int nslot = (c+2) % 3;
            const float* xc = xbase + (long long)(c+2)*8*QL;
            #pragma unroll
            for (int u = 0; u < 4; ++u){
                int ch = row0 + u*2;
                cp_async16(sx_base + nslot*(K2_STAGE_FLOATS*4) + ch*2048 + off0,
                           (const char*)(xc + (long long)ch*QL) + off0);
            }
            asm volatile("cp.async.commit_group;");
        }
        const float* rowc = ssrc + c*(8*20);
        const float* sxc  = sx + (c % 3)*K2_STAGE_FLOATS + tid*2;
        #pragma unroll
        for (int j = 0; j < 8; ++j){
            float2 xv = *reinterpret_cast<const float2*>(sxc + j*512);
            k2_consume(xv, rowc + j*20, a0, a1);
        }
    }

    // epilogue: softmax (max-free: |score| << 88) + cs dot
    float sa[SL], sb[SL];
    #pragma unroll
    for (int p = 0; p < SP; ++p){
        unpack2(a0[p], sa[2*p], sa[2*p+1]);
        unpack2(a1[p], sb[2*p], sb[2*p+1]);
    }
    float d0 = 0.f, d1 = 0.f, n0 = 0.f, n1 = 0.f;
    #pragma unroll
    for (int s = 0; s < SL; ++s){
        float e0 = __expf(sa[s]);
        float e1 = __expf(sb[s]);
        float cc = scs[s];
        d0 += e0; d1 += e1;
        n0 = fmaf(e0, cc, n0);
        n1 = fmaf(e1, cc, n1);
    }
    const float cb = conv_b[0];
    float2 o2 = make_float2(n0/d0 + cb, n1/d1 + cb);
    *reinterpret_cast<float2*>(&g_wctx2[b*QL + q0 + tid*2]) = o2;
}

// ---------------------------------------------------------------------------
// k3: split-K FC partials (R3-proven: coalesced [split][a][b] stores,
// separate launch — the threadfence fusion was an ~8us regression).
// ---------------------------------------------------------------------------
__global__ void __launch_bounds__(256) k3_fc(const float* __restrict__ fcw){
    const int split = blockIdx.x;
    const int k0    = split * KCH;
    const int tid   = threadIdx.x;
    const int lane  = tid & 31;
    const int w     = tid >> 5;

    __shared__ float sm[KCH*33];   // [k][b], padded (33.8 KB)
    for (int idx = tid; idx < BB*KCH; idx += 256){
        int b = idx >> 8;          // /256
        int k = idx & 255;
        sm[k*33 + b] = g_wctx2[b*QL + k0 + k];
    }
    __syncthreads();

    const int a0 = blockIdx.y * 16 + w * 2;   // a-pair {a0, a0+1}
    if (a0 >= ADIM) return;

    const float4* f0 = reinterpret_cast<const float4*>(fcw + (long long)(a0  )*QL + k0);
    const float4* f1 = reinterpret_cast<const float4*>(fcw + (long long)(a0+1)*QL + k0);
    float acc0 = 0.f, acc1 = 0.f;
    #pragma unroll 8
    for (int kq = 0; kq < KCH/4; ++kq){
        float4 x0 = __ldg(f0 + kq);
        float4 x1 = __ldg(f1 + kq);
        const int k = kq*4;
        float v0 = sm[(k+0)*33 + lane];
        float v1 = sm[(k+1)*33 + lane];
        float v2 = sm[(k+2)*33 + lane];
        float v3 = sm[(k+3)*33 + lane];
        acc0 = fmaf(x0.x, v0, acc0);  acc1 = fmaf(x1.x, v0, acc1);
        acc0 = fmaf(x0.y, v1, acc0);  acc1 = fmaf(x1.y, v1, acc1);
        acc0 = fmaf(x0.z, v2, acc0);  acc1 = fmaf(x1.z, v2, acc1);
        acc0 = fmaf(x0.w, v3, acc0);  acc1 = fmaf(x1.w, v3, acc1);
    }
    g_partial[split*(ADIM*BB) + (a0  )*BB + lane] = acc0;
    g_partial[split*(ADIM*BB) + (a0+1)*BB + lane] = acc1;
}

// ---------------------------------------------------------------------------
// k4: parallel reduce of split partials (R3-proven, separate launch).
// ---------------------------------------------------------------------------
__global__ void __launch_bounds__(256) k4_reduce(const float* __restrict__ fcb,
                                                 float* __restrict__ out){
    const int a   = blockIdx.x;          // 0..99
    const int tid = threadIdx.x;
    const int b   = tid & 31;
    const int g   = tid >> 5;            // 0..7

    float acc = 0.f;
    #pragma unroll
    for (int sp = g; sp < NSPLIT; sp += 8)
        acc += g_partial[sp*(ADIM*BB) + a*BB + b];

    __shared__ float red[256];
    red[tid] = acc;
    __syncthreads();
    if (g == 0){
        float v = red[b] + red[b+32] + red[b+64] + red[b+96]
                + red[b+128] + red[b+160] + red[b+192] + red[b+224];
        out[b*ADIM + a] = v + fcb[a];
    }
}

extern "C" void kernel_launch(void* const* d_in, const int* in_sizes, int n_in,
                              void* d_out, int out_size){
    const float* inputs     = (const float*)d_in[0];  // [32,64,128,128]
    const float* context    = (const float*)d_in[1];  // [32,768,18]
    const float* conv_ctx_w = (const float*)d_in[2];  // [64,768]
    const float* conv_w     = (const float*)d_in[3];  // [64]
    const float* conv_b     = (const float*)d_in[4];  // [1]
    const float* fc_w       = (const float*)d_in[5];  // [100,16384]
    const float* fc_b       = (const float*)d_in[6];  // [100]
    float* out = (float*)d_out;                        // [32,100]

    cudaFuncSetAttribute(k2_attn, cudaFuncAttributeMaxDynamicSharedMemorySize,
                         K2_SMEM_BYTES);

    k1_sourceT<<<dim3(8, BB), 256>>>(context, conv_ctx_w);
    k2_attn   <<<dim3(QL/512, BB), 256, K2_SMEM_BYTES>>>(inputs, conv_w, conv_b);
    k3_fc     <<<dim3(NSPLIT, 7), 256>>>(fc_w);
    k4_reduce <<<ADIM, 256>>>(fc_b, out);
}